// round 16
// baseline (speedup 1.0000x reference)
#include <cuda_runtime.h>
#include <cuda_fp16.h>
#include <cstdint>

// Problem constants
#define NWIN  4096
#define NTOK  64
#define DIM   192
#define HEADS 6
#define QK_SCALE 0.17677669529663687f    // 32^-0.5
#define RCP_LN2  1.4426950408889634f     // log2(e)

#define NTHREADS 768   // 24 warps

// smem (uint32 words). APAD/VPAD mod 32 == 4 -> fragment banks conflict-free.
#define APAD 100   // 96 packed words (192 fp16-pairs) + 4 pad
#define VPAD 36    // 32 packed words (64 j-pairs) + 4 pad
#define OFF_AB  0                        // [64][100] x big, later O big
#define OFF_AS  (OFF_AB  + 64*APAD)      // [64][100] x small, later O small
#define OFF_QB  (OFF_AS  + 64*APAD)
#define OFF_QS  (OFF_QB  + 64*APAD)
#define OFF_KB  (OFF_QS  + 64*APAD)      // K big only (B-side single-rounded)
#define OFF_VTB (OFF_KB  + 64*APAD)      // [192][36] V^T big only
#define SMEM_WORDS (OFF_VTB + 192*VPAD)  // 38912 words = 155648 B

// Device-global prepacked data (weights: BIG pair only -> uint2)
#define NQ_FRAG (12 * 72 * 32)
#define NP_FRAG (12 * 24 * 32)
#define NBF     (HEADS * 4 * 8 * 32)     // bias in C-fragment layout (pre-scaled by log2e)
__device__ uint2  g_wqkv[NQ_FRAG];   // {big_b0, big_b1} (fp16x2 each)
__device__ uint2  g_wproj[NP_FRAG];
__device__ float4 g_biasf[NBF];      // {c0,c1,c2,c3} per lane

__device__ __forceinline__ uint32_t packh2(__half2 p) {
    return *reinterpret_cast<uint32_t*>(&p);
}
__device__ __forceinline__ void split2h(float v0, float v1, uint32_t& big, uint32_t& sml) {
    __half2 b = __floats2half2_rn(v0, v1);
    float r0 = v0 - __half2float(__low2half(b));
    float r1 = v1 - __half2float(__high2half(b));
    __half2 s = __floats2half2_rn(r0, r1);
    big = packh2(b); sml = packh2(s);
}

// fp16 inputs, fp32 accumulators (main terms)
#define MMA_F16_F32(C, A0, A1, A2, A3, B0, B1)                                       \
    asm("mma.sync.aligned.m16n8k16.row.col.f32.f16.f16.f32 "                         \
        "{%0,%1,%2,%3},{%4,%5,%6,%7},{%8,%9},{%0,%1,%2,%3};"                         \
        : "+f"((C)[0]), "+f"((C)[1]), "+f"((C)[2]), "+f"((C)[3])                     \
        : "r"(A0), "r"(A1), "r"(A2), "r"(A3), "r"(B0), "r"(B1))

// fp16 inputs, fp16 accumulators (A-side correction terms; D[0]={c0,c1}, D[1]={c2,c3})
#define MMA_F16_F16(D, A0, A1, A2, A3, B0, B1)                                       \
    asm("mma.sync.aligned.m16n8k16.row.col.f16.f16.f16.f16 "                         \
        "{%0,%1},{%2,%3,%4,%5},{%6,%7},{%0,%1};"                                     \
        : "+r"((D)[0]), "+r"((D)[1])                                                 \
        : "r"(A0), "r"(A1), "r"(A2), "r"(A3), "r"(B0), "r"(B1))

#define LDM_X4(R0, R1, R2, R3, PTR)                                                  \
    asm volatile("ldmatrix.sync.aligned.m8n8.x4.shared.b16 {%0,%1,%2,%3}, [%4];"     \
        : "=r"(R0), "=r"(R1), "=r"(R2), "=r"(R3)                                     \
        : "r"((uint32_t)__cvta_generic_to_shared(PTR)))

#define LDM_X2(R0, R1, PTR)                                                          \
    asm volatile("ldmatrix.sync.aligned.m8n8.x2.shared.b16 {%0,%1}, [%2];"           \
        : "=r"(R0), "=r"(R1)                                                         \
        : "r"((uint32_t)__cvta_generic_to_shared(PTR)))

__device__ __forceinline__ float h2lo(uint32_t u) {
    __half2 h = *reinterpret_cast<__half2*>(&u); return __half2float(__low2half(h));
}
__device__ __forceinline__ float h2hi(uint32_t u) {
    __half2 h = *reinterpret_cast<__half2*>(&u); return __half2float(__high2half(h));
}

// Prep: pack weights (big fp16 pair) into B-fragment order; bias (×log2e) into C-frag layout.
__global__ void prep_kernel(const float* __restrict__ qkv_w,
                            const float* __restrict__ proj_w,
                            const float* __restrict__ bias_table,
                            const int* __restrict__ rel_index) {
    int idx = blockIdx.x * blockDim.x + threadIdx.x;
    if (idx < NQ_FRAG) {
        int lane = idx & 31, nt = (idx >> 5) % 72, ks = idx / (72 * 32);
        int g = lane >> 2, t = lane & 3;
        int n = nt * 8 + g, k0 = ks * 16 + 2 * t;
        uint32_t bb0 = packh2(__floats2half2_rn(qkv_w[n * DIM + k0],     qkv_w[n * DIM + k0 + 1]));
        uint32_t bb1 = packh2(__floats2half2_rn(qkv_w[n * DIM + k0 + 8], qkv_w[n * DIM + k0 + 9]));
        g_wqkv[idx] = make_uint2(bb0, bb1);
    } else if (idx < NQ_FRAG + NP_FRAG) {
        int j = idx - NQ_FRAG;
        int lane = j & 31, nt = (j >> 5) % 24, ks = j / (24 * 32);
        int g = lane >> 2, t = lane & 3;
        int n = nt * 8 + g, k0 = ks * 16 + 2 * t;
        uint32_t bb0 = packh2(__floats2half2_rn(proj_w[n * DIM + k0],     proj_w[n * DIM + k0 + 1]));
        uint32_t bb1 = packh2(__floats2half2_rn(proj_w[n * DIM + k0 + 8], proj_w[n * DIM + k0 + 9]));
        g_wproj[j] = make_uint2(bb0, bb1);
    } else if (idx < NQ_FRAG + NP_FRAG + NBF) {
        int e = idx - NQ_FRAG - NP_FRAG;
        int lane = e & 31, nt = (e >> 5) & 7, mt = (e >> 8) & 3, h = e >> 10;
        int g = lane >> 2, t = lane & 3;
        int r0 = mt * 16 + g, c0 = nt * 8 + 2 * t;
        float4 v;
        v.x = bias_table[rel_index[r0 * NTOK + c0]           * HEADS + h] * RCP_LN2;
        v.y = bias_table[rel_index[r0 * NTOK + c0 + 1]       * HEADS + h] * RCP_LN2;
        v.z = bias_table[rel_index[(r0 + 8) * NTOK + c0]     * HEADS + h] * RCP_LN2;
        v.w = bias_table[rel_index[(r0 + 8) * NTOK + c0 + 1] * HEADS + h] * RCP_LN2;
        g_biasf[e] = v;
    }
}

__global__ __launch_bounds__(NTHREADS, 1)
void msa_fused_kernel(const float* __restrict__ x,
                      const float* __restrict__ qkv_b,
                      const float* __restrict__ proj_b,
                      float* __restrict__ out)
{
    extern __shared__ uint32_t smu[];
    uint32_t* AB  = smu + OFF_AB;   // x big -> later O big
    uint32_t* AS  = smu + OFF_AS;
    uint32_t* QB  = smu + OFF_QB;
    uint32_t* QS  = smu + OFF_QS;
    uint32_t* KB  = smu + OFF_KB;
    uint32_t* VTB = smu + OFF_VTB;
    __half* VTB16 = reinterpret_cast<__half*>(VTB);

    const int tid  = threadIdx.x;
    const int lane = tid & 31;
    const int warp = tid >> 5;     // 0..23
    const int wc   = warp % 12;    // column group (48 QKV cols / 16 proj cols)
    const int mh   = warp / 12;    // m-half (rows mh*32 .. mh*32+31)
    const int g    = lane >> 2;
    const int t    = lane & 3;
    const int b    = blockIdx.x;
    const float* xb = x + (size_t)b * (NTOK * DIM);
    float* ob       = out + (size_t)b * (NTOK * DIM);

    // ldmatrix lane address pieces
    const int lrow  = (lane & 7) + 8 * ((lane >> 3) & 1);   // A-frag x4
    const int lcol  = 4 * (lane >> 4);
    const int klane = lane & 15;                            // B-frag x2
    const int krow  = klane & 7;
    const int kcol  = 4 * (klane >> 3);

    // ---- Stage x once as big/small fp16x2 (fragment-load layout) ----
    #pragma unroll
    for (int it = 0; it < 4; ++it) {
        int idx = tid + NTHREADS * it;     // 0..3071
        int r  = idx / 48;
        int c4 = (idx % 48) * 4;
        float4 v = *reinterpret_cast<const float4*>(xb + r * DIM + c4);
        uint32_t b0, s0, b1, s1;
        split2h(v.x, v.y, b0, s0);
        split2h(v.z, v.w, b1, s1);
        int w = r * APAD + (c4 >> 1);
        AB[w] = b0; AB[w + 1] = b1;
        AS[w] = s0; AS[w + 1] = s1;
    }
    __syncthreads();

    // ================= Phase 1: QKV GEMM (2-term: Ab*Bb f32-acc + As*Bb f16-acc) ========
    // Warp (mh, wc): rows [32mh, 32mh+32), cols [48wc, 48wc+48); 2 passes x 3 n-tiles.
    // B weights software-pipelined one ksg iteration ahead.
    {
        const int abase0 = (mh * 32 + lrow) * APAD + lcol;
        const int abase1 = abase0 + 16 * APAD;

        #pragma unroll 1
        for (int pass = 0; pass < 2; ++pass) {
            float c[2][3][4];
            uint32_t d[2][3][2];
            #pragma unroll
            for (int mt = 0; mt < 2; ++mt)
                #pragma unroll
                for (int nt = 0; nt < 3; ++nt) {
                    c[mt][nt][0] = c[mt][nt][1] = c[mt][nt][2] = c[mt][nt][3] = 0.f;
                    d[mt][nt][0] = d[mt][nt][1] = 0u;
                }

            // prologue prefetch: B for ksg=0
            uint2 B2[3];
            #pragma unroll
            for (int nt = 0; nt < 3; ++nt)
                B2[nt] = g_wqkv[(wc * 6 + pass * 3 + nt) * 32 + lane];

            #pragma unroll
            for (int ksg = 0; ksg < 12; ++ksg) {
                uint32_t ab[2][4], as[2][4];
                LDM_X4(ab[0][0], ab[0][1], ab[0][2], ab[0][3], AB + abase0 + ksg * 8);
                LDM_X4(ab[1][0], ab[1][1], ab[1][2], ab[1][3], AB + abase1 + ksg * 8);
                LDM_X4(as[0][0], as[0][1], as[0][2], as[0][3], AS + abase0 + ksg * 8);
                LDM_X4(as[1][0], as[1][1], as[1][2], as[1][3], AS + abase1 + ksg * 8);
                // prefetch B for ksg+1 (overlaps the mma block below)
                uint2 B2n[3];
                if (ksg < 11) {
                    #pragma unroll
                    for (int nt = 0; nt < 3; ++nt)
                        B2n[nt] = g_wqkv[((ksg + 1) * 72 + wc * 6 + pass * 3 + nt) * 32 + lane];
                }
                #pragma unroll
                for (int nt = 0; nt < 3; ++nt) {
                    MMA_F16_F32(c[0][nt], ab[0][0], ab[0][1], ab[0][2], ab[0][3], B2[nt].x, B2[nt].y);
                    MMA_F16_F32(c[1][nt], ab[1][0], ab[1][1], ab[1][2], ab[1][3], B2[nt].x, B2[nt].y);
                    MMA_F16_F16(d[0][nt], as[0][0], as[0][1], as[0][2], as[0][3], B2[nt].x, B2[nt].y);
                    MMA_F16_F16(d[1][nt], as[1][0], as[1][1], as[1][2], as[1][3], B2[nt].x, B2[nt].y);
                }
                if (ksg < 11) {
                    #pragma unroll
                    for (int nt = 0; nt < 3; ++nt) B2[nt] = B2n[nt];
                }
            }
            // Epilogue: merge corr, + bias, store Q (split, pre-scaled by log2e) / K / V^T.
            #pragma unroll
            for (int nt = 0; nt < 3; ++nt) {
                int colbase = wc * 48 + (pass * 3 + nt) * 8 + 2 * t;   // even
                float bias0 = qkv_b[colbase], bias1 = qkv_b[colbase + 1];
                #pragma unroll
                for (int mt = 0; mt < 2; ++mt) {
                    float vv[4];
                    vv[0] = c[mt][nt][0] + h2lo(d[mt][nt][0]) + bias0;
                    vv[1] = c[mt][nt][1] + h2hi(d[mt][nt][0]) + bias1;
                    vv[2] = c[mt][nt][2] + h2lo(d[mt][nt][1]) + bias0;
                    vv[3] = c[mt][nt][3] + h2hi(d[mt][nt][1]) + bias1;
                    #pragma unroll
                    for (int rr = 0; rr < 2; ++rr) {
                        int row = mh * 32 + mt * 16 + g + 8 * rr;
                        float v0 = vv[rr * 2 + 0], v1 = vv[rr * 2 + 1];
                        if (colbase < DIM) {
                            uint32_t bb, ss;
                            const float QSC = QK_SCALE * RCP_LN2;
                            split2h(v0 * QSC, v1 * QSC, bb, ss);
                            int w = row * APAD + (colbase >> 1);
                            QB[w] = bb; QS[w] = ss;
                        } else if (colbase < 2 * DIM) {
                            int w = row * APAD + ((colbase - DIM) >> 1);
                            KB[w] = packh2(__floats2half2_rn(v0, v1));
                        } else {
                            int d0 = colbase - 2 * DIM;
                            VTB16[d0 * (2 * VPAD) + row]       = __float2half_rn(v0);
                            VTB16[(d0 + 1) * (2 * VPAD) + row] = __float2half_rn(v1);
                        }
                    }
                }
            }
        }
    }
    __syncthreads();

    // ================= Phase 2: attention — one job per warp (24 jobs, 24 warps) =========
    {
        const int job = warp;
        const int h = job >> 2, mt = job & 3;
        const int r0 = mt * 16 + g;

        uint32_t qb[2][4], qs[2][4];
        const int qbase = (mt * 16 + lrow) * APAD + h * 16 + lcol;
        #pragma unroll
        for (int kc = 0; kc < 2; ++kc) {
            LDM_X4(qb[kc][0], qb[kc][1], qb[kc][2], qb[kc][3], QB + qbase + kc * 8);
            LDM_X4(qs[kc][0], qs[kc][1], qs[kc][2], qs[kc][3], QS + qbase + kc * 8);
        }
        // Bias (already ×log2e) into f32 S accumulators; f16 corr accs zeroed
        float s[8][4];
        uint32_t sc[8][2];
        #pragma unroll
        for (int nt = 0; nt < 8; ++nt) {
            float4 bf = g_biasf[((h * 4 + mt) * 8 + nt) * 32 + lane];
            s[nt][0] = bf.x; s[nt][1] = bf.y; s[nt][2] = bf.z; s[nt][3] = bf.w;
            sc[nt][0] = 0u; sc[nt][1] = 0u;
        }
        // S += (Qb+Qs) K^T  (K single-rounded)
        #pragma unroll
        for (int nt = 0; nt < 8; ++nt) {
            const int kb_base = (nt * 8 + krow) * APAD + h * 16 + kcol;
            #pragma unroll
            for (int kc = 0; kc < 2; ++kc) {
                uint32_t kb0, kb1;
                LDM_X2(kb0, kb1, KB + kb_base + kc * 8);
                MMA_F16_F32(s[nt],  qb[kc][0], qb[kc][1], qb[kc][2], qb[kc][3], kb0, kb1);
                MMA_F16_F16(sc[nt], qs[kc][0], qs[kc][1], qs[kc][2], qs[kc][3], kb0, kb1);
            }
        }
        // Merge corrections
        #pragma unroll
        for (int nt = 0; nt < 8; ++nt) {
            s[nt][0] += h2lo(sc[nt][0]); s[nt][1] += h2hi(sc[nt][0]);
            s[nt][2] += h2lo(sc[nt][1]); s[nt][3] += h2hi(sc[nt][1]);
        }
        // Register softmax in base-2 (scores pre-scaled by log2e)
        float mlo = fmaxf(s[0][0], s[0][1]), mhi = fmaxf(s[0][2], s[0][3]);
        #pragma unroll
        for (int nt = 1; nt < 8; ++nt) {
            mlo = fmaxf(mlo, fmaxf(s[nt][0], s[nt][1]));
            mhi = fmaxf(mhi, fmaxf(s[nt][2], s[nt][3]));
        }
        mlo = fmaxf(mlo, __shfl_xor_sync(0xffffffffu, mlo, 1));
        mlo = fmaxf(mlo, __shfl_xor_sync(0xffffffffu, mlo, 2));
        mhi = fmaxf(mhi, __shfl_xor_sync(0xffffffffu, mhi, 1));
        mhi = fmaxf(mhi, __shfl_xor_sync(0xffffffffu, mhi, 2));
        float llo = 0.f, lhi = 0.f;
        #pragma unroll
        for (int nt = 0; nt < 8; ++nt) {
            s[nt][0] = exp2f(s[nt][0] - mlo); s[nt][1] = exp2f(s[nt][1] - mlo);
            s[nt][2] = exp2f(s[nt][2] - mhi); s[nt][3] = exp2f(s[nt][3] - mhi);
            llo += s[nt][0] + s[nt][1];
            lhi += s[nt][2] + s[nt][3];
        }
        llo += __shfl_xor_sync(0xffffffffu, llo, 1);
        llo += __shfl_xor_sync(0xffffffffu, llo, 2);
        lhi += __shfl_xor_sync(0xffffffffu, lhi, 1);
        lhi += __shfl_xor_sync(0xffffffffu, lhi, 2);

        // Re-pack S C-fragments into P A-fragments (registers only, fp16 2-split)
        uint32_t pb[4][4], ps[4][4];
        #pragma unroll
        for (int kc = 0; kc < 4; ++kc) {
            split2h(s[2 * kc][0],     s[2 * kc][1],     pb[kc][0], ps[kc][0]);
            split2h(s[2 * kc][2],     s[2 * kc][3],     pb[kc][1], ps[kc][1]);
            split2h(s[2 * kc + 1][0], s[2 * kc + 1][1], pb[kc][2], ps[kc][2]);
            split2h(s[2 * kc + 1][2], s[2 * kc + 1][3], pb[kc][3], ps[kc][3]);
        }
        // O = (Pb+Ps) V  (V single-rounded)
        float o[4][4];
        uint32_t oc[4][2];
        #pragma unroll
        for (int nt2 = 0; nt2 < 4; ++nt2) {
            o[nt2][0] = o[nt2][1] = o[nt2][2] = o[nt2][3] = 0.f;
            oc[nt2][0] = 0u; oc[nt2][1] = 0u;
        }
        #pragma unroll
        for (int nt2 = 0; nt2 < 4; ++nt2) {
            const int vb_base = (h * 32 + nt2 * 8 + krow) * VPAD + kcol;
            #pragma unroll
            for (int kc = 0; kc < 4; ++kc) {
                uint32_t vb0, vb1;
                LDM_X2(vb0, vb1, VTB + vb_base + kc * 8);
                MMA_F16_F32(o[nt2],  pb[kc][0], pb[kc][1], pb[kc][2], pb[kc][3], vb0, vb1);
                MMA_F16_F16(oc[nt2], ps[kc][0], ps[kc][1], ps[kc][2], ps[kc][3], vb0, vb1);
            }
        }
        // Merge corr, normalize, write O as packed big/small into AB/AS
        float lilo = 1.f / llo, lihi = 1.f / lhi;
        #pragma unroll
        for (int nt2 = 0; nt2 < 4; ++nt2) {
            float o0 = o[nt2][0] + h2lo(oc[nt2][0]);
            float o1 = o[nt2][1] + h2hi(oc[nt2][0]);
            float o2 = o[nt2][2] + h2lo(oc[nt2][1]);
            float o3 = o[nt2][3] + h2hi(oc[nt2][1]);
            int w = r0 * APAD + h * 16 + nt2 * 4 + t;
            uint32_t bb, ss;
            split2h(o0 * lilo, o1 * lilo, bb, ss);
            AB[w] = bb; AS[w] = ss;
            split2h(o2 * lihi, o3 * lihi, bb, ss);
            AB[w + 8 * APAD] = bb; AS[w + 8 * APAD] = ss;
        }
    }
    __syncthreads();

    // ================= Phase 3: proj GEMM (2-term), B prefetched one ksg ahead =========
    {
        float c[2][2][4];
        uint32_t d[2][2][2];
        #pragma unroll
        for (int mt = 0; mt < 2; ++mt)
            #pragma unroll
            for (int nt = 0; nt < 2; ++nt) {
                c[mt][nt][0] = c[mt][nt][1] = c[mt][nt][2] = c[mt][nt][3] = 0.f;
                d[mt][nt][0] = d[mt][nt][1] = 0u;
            }

        const int abase0 = (mh * 32 + lrow) * APAD + lcol;
        const int abase1 = abase0 + 16 * APAD;

        uint2 B2[2];
        #pragma unroll
        for (int nt = 0; nt < 2; ++nt)
            B2[nt] = g_wproj[(wc * 2 + nt) * 32 + lane];

        #pragma unroll
        for (int ksg = 0; ksg < 12; ++ksg) {
            uint32_t ab[2][4], as[2][4];
            LDM_X4(ab[0][0], ab[0][1], ab[0][2], ab[0][3], AB + abase0 + ksg * 8);
            LDM_X4(ab[1][0], ab[1][1], ab[1][2], ab[1][3], AB + abase1 + ksg * 8);
            LDM_X4(as[0][0], as[0][1], as[0][2], as[0][3], AS + abase0 + ksg * 8);
            LDM_X4(as[1][0], as[1][1], as[1][2], as[1][3], AS + abase1 + ksg * 8);
            uint2 B2n[2];
            if (ksg < 11) {
                #pragma unroll
                for (int nt = 0; nt < 2; ++nt)
                    B2n[nt] = g_wproj[((ksg + 1) * 24 + wc * 2 + nt) * 32 + lane];
            }
            #pragma unroll
            for (int nt = 0; nt < 2; ++nt) {
                MMA_F16_F32(c[0][nt], ab[0][0], ab[0][1], ab[0][2], ab[0][3], B2[nt].x, B2[nt].y);
                MMA_F16_F32(c[1][nt], ab[1][0], ab[1][1], ab[1][2], ab[1][3], B2[nt].x, B2[nt].y);
                MMA_F16_F16(d[0][nt], as[0][0], as[0][1], as[0][2], as[0][3], B2[nt].x, B2[nt].y);
                MMA_F16_F16(d[1][nt], as[1][0], as[1][1], as[1][2], as[1][3], B2[nt].x, B2[nt].y);
            }
            if (ksg < 11) {
                #pragma unroll
                for (int nt = 0; nt < 2; ++nt) B2[nt] = B2n[nt];
            }
        }
        // Epilogue: merge corr + bias, write to gmem
        #pragma unroll
        for (int nt = 0; nt < 2; ++nt) {
            int colbase = wc * 16 + nt * 8 + 2 * t;
            float b0 = proj_b[colbase], b1 = proj_b[colbase + 1];
            #pragma unroll
            for (int mt = 0; mt < 2; ++mt) {
                float vv[4];
                vv[0] = c[mt][nt][0] + h2lo(d[mt][nt][0]) + b0;
                vv[1] = c[mt][nt][1] + h2hi(d[mt][nt][0]) + b1;
                vv[2] = c[mt][nt][2] + h2lo(d[mt][nt][1]) + b0;
                vv[3] = c[mt][nt][3] + h2hi(d[mt][nt][1]) + b1;
                #pragma unroll
                for (int rr = 0; rr < 2; ++rr) {
                    int row = mh * 32 + mt * 16 + g + 8 * rr;
                    float2 v;
                    v.x = vv[rr * 2 + 0];
                    v.y = vv[rr * 2 + 1];
                    *reinterpret_cast<float2*>(ob + row * DIM + colbase) = v;
                }
            }
        }
    }
}

extern "C" void kernel_launch(void* const* d_in, const int* in_sizes, int n_in,
                              void* d_out, int out_size) {
    const float* x          = (const float*)d_in[0];
    const float* qkv_w      = (const float*)d_in[1];
    const float* qkv_b      = (const float*)d_in[2];
    const float* proj_w     = (const float*)d_in[3];
    const float* proj_b     = (const float*)d_in[4];
    const float* bias_table = (const float*)d_in[5];
    const int*   rel_index  = (const int*)d_in[6];
    float* out = (float*)d_out;

    cudaFuncSetAttribute(msa_fused_kernel, cudaFuncAttributeMaxDynamicSharedMemorySize,
                         SMEM_WORDS * (int)sizeof(uint32_t));

    int prep_n = NQ_FRAG + NP_FRAG + NBF;
    prep_kernel<<<(prep_n + 255) / 256, 256>>>(qkv_w, proj_w, bias_table, rel_index);
    msa_fused_kernel<<<NWIN, NTHREADS, SMEM_WORDS * sizeof(uint32_t)>>>(x, qkv_b, proj_b, out);
}

// round 17
// speedup vs baseline: 1.2229x; 1.2229x over previous
#include <cuda_runtime.h>
#include <cuda_fp16.h>
#include <cstdint>

// Problem constants
#define NWIN  4096
#define NTOK  64
#define DIM   192
#define HEADS 6
#define QK_SCALE 0.17677669529663687f   // 32^-0.5

#define NTHREADS 768   // 24 warps

// smem (uint32 words). APAD/VPAD mod 32 == 4 -> fragment banks conflict-free.
#define APAD 100   // 96 packed words (192 fp16-pairs) + 4 pad
#define VPAD 36    // 32 packed words (64 j-pairs) + 4 pad
#define OFF_AB  0                        // [64][100] x big, later O big
#define OFF_AS  (OFF_AB  + 64*APAD)      // [64][100] x small, later O small
#define OFF_QB  (OFF_AS  + 64*APAD)
#define OFF_QS  (OFF_QB  + 64*APAD)
#define OFF_KB  (OFF_QS  + 64*APAD)      // K big only (B-side single-rounded)
#define OFF_VTB (OFF_KB  + 64*APAD)      // [192][36] V^T big only
#define SMEM_WORDS (OFF_VTB + 192*VPAD)  // 38912 words = 155648 B

// Device-global prepacked data (weights: BIG pair only -> uint2)
#define NQ_FRAG (12 * 72 * 32)
#define NP_FRAG (12 * 24 * 32)
#define NBF     (HEADS * 4 * 8 * 32)     // bias in C-fragment layout
__device__ uint2  g_wqkv[NQ_FRAG];   // {big_b0, big_b1} (fp16x2 each), balanced Q/K/V interleave
__device__ uint2  g_wproj[NP_FRAG];
__device__ float4 g_biasf[NBF];      // {c0,c1,c2,c3} per lane

// Balanced ntile map: packed slot (wcp, j) -> global qkv output ntile.
// j 0,1 -> Q ntiles (cols 0..191); j 2,3 -> K; j 4,5 -> V. Each warp: 2Q+2K+2V.
__host__ __device__ __forceinline__ int qkv_ntile(int wcp, int j) {
    if (j < 2)  return wcp * 2 + j;            // Q
    if (j < 4)  return 24 + wcp * 2 + (j - 2); // K
    return 48 + wcp * 2 + (j - 4);             // V
}

__device__ __forceinline__ uint32_t packh2(__half2 p) {
    return *reinterpret_cast<uint32_t*>(&p);
}
__device__ __forceinline__ void split2h(float v0, float v1, uint32_t& big, uint32_t& sml) {
    __half2 b = __floats2half2_rn(v0, v1);
    float r0 = v0 - __half2float(__low2half(b));
    float r1 = v1 - __half2float(__high2half(b));
    __half2 s = __floats2half2_rn(r0, r1);
    big = packh2(b); sml = packh2(s);
}

// fp16 inputs, fp32 accumulators (main terms)
#define MMA_F16_F32(C, A0, A1, A2, A3, B0, B1)                                       \
    asm("mma.sync.aligned.m16n8k16.row.col.f32.f16.f16.f32 "                         \
        "{%0,%1,%2,%3},{%4,%5,%6,%7},{%8,%9},{%0,%1,%2,%3};"                         \
        : "+f"((C)[0]), "+f"((C)[1]), "+f"((C)[2]), "+f"((C)[3])                     \
        : "r"(A0), "r"(A1), "r"(A2), "r"(A3), "r"(B0), "r"(B1))

// fp16 inputs, fp16 accumulators (A-side correction terms; D[0]={c0,c1}, D[1]={c2,c3})
#define MMA_F16_F16(D, A0, A1, A2, A3, B0, B1)                                       \
    asm("mma.sync.aligned.m16n8k16.row.col.f16.f16.f16.f16 "                         \
        "{%0,%1},{%2,%3,%4,%5},{%6,%7},{%0,%1};"                                     \
        : "+r"((D)[0]), "+r"((D)[1])                                                 \
        : "r"(A0), "r"(A1), "r"(A2), "r"(A3), "r"(B0), "r"(B1))

#define LDM_X4(R0, R1, R2, R3, PTR)                                                  \
    asm volatile("ldmatrix.sync.aligned.m8n8.x4.shared.b16 {%0,%1,%2,%3}, [%4];"     \
        : "=r"(R0), "=r"(R1), "=r"(R2), "=r"(R3)                                     \
        : "r"((uint32_t)__cvta_generic_to_shared(PTR)))

#define LDM_X2(R0, R1, PTR)                                                          \
    asm volatile("ldmatrix.sync.aligned.m8n8.x2.shared.b16 {%0,%1}, [%2];"           \
        : "=r"(R0), "=r"(R1)                                                         \
        : "r"((uint32_t)__cvta_generic_to_shared(PTR)))

__device__ __forceinline__ float h2lo(uint32_t u) {
    __half2 h = *reinterpret_cast<__half2*>(&u); return __half2float(__low2half(h));
}
__device__ __forceinline__ float h2hi(uint32_t u) {
    __half2 h = *reinterpret_cast<__half2*>(&u); return __half2float(__high2half(h));
}

// Prep: pack weights (big fp16 pair) into B-fragment order with balanced Q/K/V
// ntile interleave; bias into C-fragment layout.
__global__ void prep_kernel(const float* __restrict__ qkv_w,
                            const float* __restrict__ proj_w,
                            const float* __restrict__ bias_table,
                            const int* __restrict__ rel_index) {
    int idx = blockIdx.x * blockDim.x + threadIdx.x;
    if (idx < NQ_FRAG) {
        int lane = idx & 31, ntp = (idx >> 5) % 72, ks = idx / (72 * 32);
        int wcp = ntp / 6, j = ntp % 6;
        int qn = qkv_ntile(wcp, j);
        int g = lane >> 2, t = lane & 3;
        int n = qn * 8 + g, k0 = ks * 16 + 2 * t;
        uint32_t bb0 = packh2(__floats2half2_rn(qkv_w[n * DIM + k0],     qkv_w[n * DIM + k0 + 1]));
        uint32_t bb1 = packh2(__floats2half2_rn(qkv_w[n * DIM + k0 + 8], qkv_w[n * DIM + k0 + 9]));
        g_wqkv[idx] = make_uint2(bb0, bb1);
    } else if (idx < NQ_FRAG + NP_FRAG) {
        int j = idx - NQ_FRAG;
        int lane = j & 31, nt = (j >> 5) % 24, ks = j / (24 * 32);
        int g = lane >> 2, t = lane & 3;
        int n = nt * 8 + g, k0 = ks * 16 + 2 * t;
        uint32_t bb0 = packh2(__floats2half2_rn(proj_w[n * DIM + k0],     proj_w[n * DIM + k0 + 1]));
        uint32_t bb1 = packh2(__floats2half2_rn(proj_w[n * DIM + k0 + 8], proj_w[n * DIM + k0 + 9]));
        g_wproj[j] = make_uint2(bb0, bb1);
    } else if (idx < NQ_FRAG + NP_FRAG + NBF) {
        int e = idx - NQ_FRAG - NP_FRAG;
        int lane = e & 31, nt = (e >> 5) & 7, mt = (e >> 8) & 3, h = e >> 10;
        int g = lane >> 2, t = lane & 3;
        int r0 = mt * 16 + g, c0 = nt * 8 + 2 * t;
        float4 v;
        v.x = bias_table[rel_index[r0 * NTOK + c0]           * HEADS + h];
        v.y = bias_table[rel_index[r0 * NTOK + c0 + 1]       * HEADS + h];
        v.z = bias_table[rel_index[(r0 + 8) * NTOK + c0]     * HEADS + h];
        v.w = bias_table[rel_index[(r0 + 8) * NTOK + c0 + 1] * HEADS + h];
        g_biasf[e] = v;
    }
}

__global__ __launch_bounds__(NTHREADS, 1)
void msa_fused_kernel(const float* __restrict__ x,
                      const float* __restrict__ qkv_b,
                      const float* __restrict__ proj_b,
                      float* __restrict__ out)
{
    extern __shared__ uint32_t smu[];
    uint32_t* AB  = smu + OFF_AB;   // x big -> later O big
    uint32_t* AS  = smu + OFF_AS;
    uint32_t* QB  = smu + OFF_QB;
    uint32_t* QS  = smu + OFF_QS;
    uint32_t* KB  = smu + OFF_KB;
    uint32_t* VTB = smu + OFF_VTB;
    __half* VTB16 = reinterpret_cast<__half*>(VTB);

    const int tid  = threadIdx.x;
    const int lane = tid & 31;
    const int warp = tid >> 5;     // 0..23
    const int wc   = warp % 12;    // column group
    const int mh   = warp / 12;    // m-half (rows mh*32 .. mh*32+31)
    const int g    = lane >> 2;
    const int t    = lane & 3;
    const int b    = blockIdx.x;
    const float* xb = x + (size_t)b * (NTOK * DIM);
    float* ob       = out + (size_t)b * (NTOK * DIM);

    // ldmatrix lane address pieces
    const int lrow  = (lane & 7) + 8 * ((lane >> 3) & 1);   // A-frag x4
    const int lcol  = 4 * (lane >> 4);
    const int klane = lane & 15;                            // B-frag x2
    const int krow  = klane & 7;
    const int kcol  = 4 * (klane >> 3);

    // ---- Stage x once as big/small fp16x2 (fragment-load layout) ----
    #pragma unroll
    for (int it = 0; it < 4; ++it) {
        int idx = tid + NTHREADS * it;     // 0..3071
        int r  = idx / 48;
        int c4 = (idx % 48) * 4;
        float4 v = *reinterpret_cast<const float4*>(xb + r * DIM + c4);
        uint32_t b0, s0, b1, s1;
        split2h(v.x, v.y, b0, s0);
        split2h(v.z, v.w, b1, s1);
        int w = r * APAD + (c4 >> 1);
        AB[w] = b0; AB[w + 1] = b1;
        AS[w] = s0; AS[w + 1] = s1;
    }
    __syncthreads();

    // ================= Phase 1: QKV GEMM, balanced 2Q+2K+2V ntiles per warp ============
    // Pass 0 (j=0,1,2): Q,Q,K — corrections on the 2 Q ntiles.
    // Pass 1 (j=3,4,5): K,V,V — big-only (K/V get fp16-rounded on store anyway).
    {
        const int abase0 = (mh * 32 + lrow) * APAD + lcol;
        const int abase1 = abase0 + 16 * APAD;

        // ---- Pass 0 ----
        {
            float c[2][3][4];
            uint32_t d[2][2][2];
            #pragma unroll
            for (int mt = 0; mt < 2; ++mt) {
                #pragma unroll
                for (int nt = 0; nt < 3; ++nt)
                    c[mt][nt][0] = c[mt][nt][1] = c[mt][nt][2] = c[mt][nt][3] = 0.f;
                d[mt][0][0] = d[mt][0][1] = d[mt][1][0] = d[mt][1][1] = 0u;
            }
            for (int ksg = 0; ksg < 12; ++ksg) {
                uint32_t ab[2][4], as[2][4];
                LDM_X4(ab[0][0], ab[0][1], ab[0][2], ab[0][3], AB + abase0 + ksg * 8);
                LDM_X4(ab[1][0], ab[1][1], ab[1][2], ab[1][3], AB + abase1 + ksg * 8);
                LDM_X4(as[0][0], as[0][1], as[0][2], as[0][3], AS + abase0 + ksg * 8);
                LDM_X4(as[1][0], as[1][1], as[1][2], as[1][3], AS + abase1 + ksg * 8);
                #pragma unroll
                for (int nt = 0; nt < 3; ++nt) {
                    uint2 B2 = g_wqkv[(ksg * 72 + wc * 6 + nt) * 32 + lane];
                    MMA_F16_F32(c[0][nt], ab[0][0], ab[0][1], ab[0][2], ab[0][3], B2.x, B2.y);
                    MMA_F16_F32(c[1][nt], ab[1][0], ab[1][1], ab[1][2], ab[1][3], B2.x, B2.y);
                    if (nt < 2) {
                        MMA_F16_F16(d[0][nt], as[0][0], as[0][1], as[0][2], as[0][3], B2.x, B2.y);
                        MMA_F16_F16(d[1][nt], as[1][0], as[1][1], as[1][2], as[1][3], B2.x, B2.y);
                    }
                }
            }
            // Epilogue pass 0: nt 0,1 -> Q (split store); nt 2 -> K (big store)
            #pragma unroll
            for (int nt = 0; nt < 2; ++nt) {
                int col = (wc * 2 + nt) * 8 + 2 * t;        // Q column, even
                float bias0 = qkv_b[col], bias1 = qkv_b[col + 1];
                #pragma unroll
                for (int mt = 0; mt < 2; ++mt) {
                    float vv[4];
                    vv[0] = c[mt][nt][0] + h2lo(d[mt][nt][0]) + bias0;
                    vv[1] = c[mt][nt][1] + h2hi(d[mt][nt][0]) + bias1;
                    vv[2] = c[mt][nt][2] + h2lo(d[mt][nt][1]) + bias0;
                    vv[3] = c[mt][nt][3] + h2hi(d[mt][nt][1]) + bias1;
                    #pragma unroll
                    for (int rr = 0; rr < 2; ++rr) {
                        int row = mh * 32 + mt * 16 + g + 8 * rr;
                        uint32_t bb, ss;
                        split2h(vv[rr * 2 + 0] * QK_SCALE, vv[rr * 2 + 1] * QK_SCALE, bb, ss);
                        int w = row * APAD + (col >> 1);
                        QB[w] = bb; QS[w] = ss;
                    }
                }
            }
            {   // nt = 2 -> K ntile wc*2
                int colk = (wc * 2) * 8 + 2 * t;
                float bias0 = qkv_b[DIM + colk], bias1 = qkv_b[DIM + colk + 1];
                #pragma unroll
                for (int mt = 0; mt < 2; ++mt)
                    #pragma unroll
                    for (int rr = 0; rr < 2; ++rr) {
                        int row = mh * 32 + mt * 16 + g + 8 * rr;
                        float v0 = c[mt][2][rr * 2 + 0] + bias0;
                        float v1 = c[mt][2][rr * 2 + 1] + bias1;
                        KB[row * APAD + (colk >> 1)] = packh2(__floats2half2_rn(v0, v1));
                    }
            }
        }
        // ---- Pass 1 (big-only) ----
        {
            float c[2][3][4];
            #pragma unroll
            for (int mt = 0; mt < 2; ++mt)
                #pragma unroll
                for (int nt = 0; nt < 3; ++nt)
                    c[mt][nt][0] = c[mt][nt][1] = c[mt][nt][2] = c[mt][nt][3] = 0.f;
            for (int ksg = 0; ksg < 12; ++ksg) {
                uint32_t ab[2][4];
                LDM_X4(ab[0][0], ab[0][1], ab[0][2], ab[0][3], AB + abase0 + ksg * 8);
                LDM_X4(ab[1][0], ab[1][1], ab[1][2], ab[1][3], AB + abase1 + ksg * 8);
                #pragma unroll
                for (int nt = 0; nt < 3; ++nt) {
                    uint2 B2 = g_wqkv[(ksg * 72 + wc * 6 + 3 + nt) * 32 + lane];
                    MMA_F16_F32(c[0][nt], ab[0][0], ab[0][1], ab[0][2], ab[0][3], B2.x, B2.y);
                    MMA_F16_F32(c[1][nt], ab[1][0], ab[1][1], ab[1][2], ab[1][3], B2.x, B2.y);
                }
            }
            // Epilogue pass 1: nt 0 -> K ntile wc*2+1; nt 1,2 -> V ntiles wc*2, wc*2+1
            {
                int colk = (wc * 2 + 1) * 8 + 2 * t;
                float bias0 = qkv_b[DIM + colk], bias1 = qkv_b[DIM + colk + 1];
                #pragma unroll
                for (int mt = 0; mt < 2; ++mt)
                    #pragma unroll
                    for (int rr = 0; rr < 2; ++rr) {
                        int row = mh * 32 + mt * 16 + g + 8 * rr;
                        float v0 = c[mt][0][rr * 2 + 0] + bias0;
                        float v1 = c[mt][0][rr * 2 + 1] + bias1;
                        KB[row * APAD + (colk >> 1)] = packh2(__floats2half2_rn(v0, v1));
                    }
            }
            #pragma unroll
            for (int nt = 1; nt < 3; ++nt) {
                int d0 = (wc * 2 + (nt - 1)) * 8 + 2 * t;   // V column, even
                float bias0 = qkv_b[2 * DIM + d0], bias1 = qkv_b[2 * DIM + d0 + 1];
                #pragma unroll
                for (int mt = 0; mt < 2; ++mt)
                    #pragma unroll
                    for (int rr = 0; rr < 2; ++rr) {
                        int row = mh * 32 + mt * 16 + g + 8 * rr;
                        float v0 = c[mt][nt][rr * 2 + 0] + bias0;
                        float v1 = c[mt][nt][rr * 2 + 1] + bias1;
                        VTB16[d0 * (2 * VPAD) + row]       = __float2half_rn(v0);
                        VTB16[(d0 + 1) * (2 * VPAD) + row] = __float2half_rn(v1);
                    }
            }
        }
    }
    __syncthreads();

    // ================= Phase 2: attention — one job per warp (24 jobs, 24 warps) =========
    {
        const int job = warp;
        const int h = job >> 2, mt = job & 3;
        const int r0 = mt * 16 + g;

        uint32_t qb[2][4], qs[2][4];
        const int qbase = (mt * 16 + lrow) * APAD + h * 16 + lcol;
        #pragma unroll
        for (int kc = 0; kc < 2; ++kc) {
            LDM_X4(qb[kc][0], qb[kc][1], qb[kc][2], qb[kc][3], QB + qbase + kc * 8);
            LDM_X4(qs[kc][0], qs[kc][1], qs[kc][2], qs[kc][3], QS + qbase + kc * 8);
        }
        // Bias into f32 S accumulators; f16 corr accs zeroed
        float s[8][4];
        uint32_t sc[8][2];
        #pragma unroll
        for (int nt = 0; nt < 8; ++nt) {
            float4 bf = g_biasf[((h * 4 + mt) * 8 + nt) * 32 + lane];
            s[nt][0] = bf.x; s[nt][1] = bf.y; s[nt][2] = bf.z; s[nt][3] = bf.w;
            sc[nt][0] = 0u; sc[nt][1] = 0u;
        }
        // S += (Qb+Qs) K^T  (K single-rounded)
        #pragma unroll
        for (int nt = 0; nt < 8; ++nt) {
            const int kb_base = (nt * 8 + krow) * APAD + h * 16 + kcol;
            #pragma unroll
            for (int kc = 0; kc < 2; ++kc) {
                uint32_t kb0, kb1;
                LDM_X2(kb0, kb1, KB + kb_base + kc * 8);
                MMA_F16_F32(s[nt],  qb[kc][0], qb[kc][1], qb[kc][2], qb[kc][3], kb0, kb1);
                MMA_F16_F16(sc[nt], qs[kc][0], qs[kc][1], qs[kc][2], qs[kc][3], kb0, kb1);
            }
        }
        // Merge corrections
        #pragma unroll
        for (int nt = 0; nt < 8; ++nt) {
            s[nt][0] += h2lo(sc[nt][0]); s[nt][1] += h2hi(sc[nt][0]);
            s[nt][2] += h2lo(sc[nt][1]); s[nt][3] += h2hi(sc[nt][1]);
        }
        // Register softmax (rows g / g+8; reduce across t-group via xor 1,2)
        float mlo = fmaxf(s[0][0], s[0][1]), mhi = fmaxf(s[0][2], s[0][3]);
        #pragma unroll
        for (int nt = 1; nt < 8; ++nt) {
            mlo = fmaxf(mlo, fmaxf(s[nt][0], s[nt][1]));
            mhi = fmaxf(mhi, fmaxf(s[nt][2], s[nt][3]));
        }
        mlo = fmaxf(mlo, __shfl_xor_sync(0xffffffffu, mlo, 1));
        mlo = fmaxf(mlo, __shfl_xor_sync(0xffffffffu, mlo, 2));
        mhi = fmaxf(mhi, __shfl_xor_sync(0xffffffffu, mhi, 1));
        mhi = fmaxf(mhi, __shfl_xor_sync(0xffffffffu, mhi, 2));
        float llo = 0.f, lhi = 0.f;
        #pragma unroll
        for (int nt = 0; nt < 8; ++nt) {
            s[nt][0] = __expf(s[nt][0] - mlo); s[nt][1] = __expf(s[nt][1] - mlo);
            s[nt][2] = __expf(s[nt][2] - mhi); s[nt][3] = __expf(s[nt][3] - mhi);
            llo += s[nt][0] + s[nt][1];
            lhi += s[nt][2] + s[nt][3];
        }
        llo += __shfl_xor_sync(0xffffffffu, llo, 1);
        llo += __shfl_xor_sync(0xffffffffu, llo, 2);
        lhi += __shfl_xor_sync(0xffffffffu, lhi, 1);
        lhi += __shfl_xor_sync(0xffffffffu, lhi, 2);

        // Re-pack S C-fragments into P A-fragments (registers only, fp16 2-split)
        uint32_t pb[4][4], ps[4][4];
        #pragma unroll
        for (int kc = 0; kc < 4; ++kc) {
            split2h(s[2 * kc][0],     s[2 * kc][1],     pb[kc][0], ps[kc][0]);
            split2h(s[2 * kc][2],     s[2 * kc][3],     pb[kc][1], ps[kc][1]);
            split2h(s[2 * kc + 1][0], s[2 * kc + 1][1], pb[kc][2], ps[kc][2]);
            split2h(s[2 * kc + 1][2], s[2 * kc + 1][3], pb[kc][3], ps[kc][3]);
        }
        // O = (Pb+Ps) V  (V single-rounded)
        float o[4][4];
        uint32_t oc[4][2];
        #pragma unroll
        for (int nt2 = 0; nt2 < 4; ++nt2) {
            o[nt2][0] = o[nt2][1] = o[nt2][2] = o[nt2][3] = 0.f;
            oc[nt2][0] = 0u; oc[nt2][1] = 0u;
        }
        #pragma unroll
        for (int nt2 = 0; nt2 < 4; ++nt2) {
            const int vb_base = (h * 32 + nt2 * 8 + krow) * VPAD + kcol;
            #pragma unroll
            for (int kc = 0; kc < 4; ++kc) {
                uint32_t vb0, vb1;
                LDM_X2(vb0, vb1, VTB + vb_base + kc * 8);
                MMA_F16_F32(o[nt2],  pb[kc][0], pb[kc][1], pb[kc][2], pb[kc][3], vb0, vb1);
                MMA_F16_F16(oc[nt2], ps[kc][0], ps[kc][1], ps[kc][2], ps[kc][3], vb0, vb1);
            }
        }
        // Merge corr, normalize, write O as packed big/small into AB/AS
        float lilo = 1.f / llo, lihi = 1.f / lhi;
        #pragma unroll
        for (int nt2 = 0; nt2 < 4; ++nt2) {
            float o0 = o[nt2][0] + h2lo(oc[nt2][0]);
            float o1 = o[nt2][1] + h2hi(oc[nt2][0]);
            float o2 = o[nt2][2] + h2lo(oc[nt2][1]);
            float o3 = o[nt2][3] + h2hi(oc[nt2][1]);
            int w = r0 * APAD + h * 16 + nt2 * 4 + t;
            uint32_t bb, ss;
            split2h(o0 * lilo, o1 * lilo, bb, ss);
            AB[w] = bb; AS[w] = ss;
            split2h(o2 * lihi, o3 * lihi, bb, ss);
            AB[w + 8 * APAD] = bb; AS[w + 8 * APAD] = ss;
        }
    }
    __syncthreads();

    // ================= Phase 3: proj GEMM (2-term), A = O fragments direct =============
    {
        float c[2][2][4];
        uint32_t d[2][2][2];
        #pragma unroll
        for (int mt = 0; mt < 2; ++mt)
            #pragma unroll
            for (int nt = 0; nt < 2; ++nt) {
                c[mt][nt][0] = c[mt][nt][1] = c[mt][nt][2] = c[mt][nt][3] = 0.f;
                d[mt][nt][0] = d[mt][nt][1] = 0u;
            }

        const int abase0 = (mh * 32 + lrow) * APAD + lcol;
        const int abase1 = abase0 + 16 * APAD;

        for (int ksg = 0; ksg < 12; ++ksg) {
            uint2 B2[2];
            #pragma unroll
            for (int nt = 0; nt < 2; ++nt)
                B2[nt] = g_wproj[(ksg * 24 + wc * 2 + nt) * 32 + lane];
            uint32_t ab[2][4], as[2][4];
            LDM_X4(ab[0][0], ab[0][1], ab[0][2], ab[0][3], AB + abase0 + ksg * 8);
            LDM_X4(ab[1][0], ab[1][1], ab[1][2], ab[1][3], AB + abase1 + ksg * 8);
            LDM_X4(as[0][0], as[0][1], as[0][2], as[0][3], AS + abase0 + ksg * 8);
            LDM_X4(as[1][0], as[1][1], as[1][2], as[1][3], AS + abase1 + ksg * 8);
            #pragma unroll
            for (int nt = 0; nt < 2; ++nt) {
                MMA_F16_F32(c[0][nt], ab[0][0], ab[0][1], ab[0][2], ab[0][3], B2[nt].x, B2[nt].y);
                MMA_F16_F32(c[1][nt], ab[1][0], ab[1][1], ab[1][2], ab[1][3], B2[nt].x, B2[nt].y);
                MMA_F16_F16(d[0][nt], as[0][0], as[0][1], as[0][2], as[0][3], B2[nt].x, B2[nt].y);
                MMA_F16_F16(d[1][nt], as[1][0], as[1][1], as[1][2], as[1][3], B2[nt].x, B2[nt].y);
            }
        }
        // Epilogue: merge corr + bias, write to gmem
        #pragma unroll
        for (int nt = 0; nt < 2; ++nt) {
            int colbase = wc * 16 + nt * 8 + 2 * t;
            float b0 = proj_b[colbase], b1 = proj_b[colbase + 1];
            #pragma unroll
            for (int mt = 0; mt < 2; ++mt) {
                float vv[4];
                vv[0] = c[mt][nt][0] + h2lo(d[mt][nt][0]) + b0;
                vv[1] = c[mt][nt][1] + h2hi(d[mt][nt][0]) + b1;
                vv[2] = c[mt][nt][2] + h2lo(d[mt][nt][1]) + b0;
                vv[3] = c[mt][nt][3] + h2hi(d[mt][nt][1]) + b1;
                #pragma unroll
                for (int rr = 0; rr < 2; ++rr) {
                    int row = mh * 32 + mt * 16 + g + 8 * rr;
                    float2 v;
                    v.x = vv[rr * 2 + 0];
                    v.y = vv[rr * 2 + 1];
                    *reinterpret_cast<float2*>(ob + row * DIM + colbase) = v;
                }
            }
        }
    }
}

extern "C" void kernel_launch(void* const* d_in, const int* in_sizes, int n_in,
                              void* d_out, int out_size) {
    const float* x          = (const float*)d_in[0];
    const float* qkv_w      = (const float*)d_in[1];
    const float* qkv_b      = (const float*)d_in[2];
    const float* proj_w     = (const float*)d_in[3];
    const float* proj_b     = (const float*)d_in[4];
    const float* bias_table = (const float*)d_in[5];
    const int*   rel_index  = (const int*)d_in[6];
    float* out = (float*)d_out;

    cudaFuncSetAttribute(msa_fused_kernel, cudaFuncAttributeMaxDynamicSharedMemorySize,
                         SMEM_WORDS * (int)sizeof(uint32_t));

    int prep_n = NQ_FRAG + NP_FRAG + NBF;
    prep_kernel<<<(prep_n + 255) / 256, 256>>>(qkv_w, proj_w, bias_table, rel_index);
    msa_fused_kernel<<<NWIN, NTHREADS, SMEM_WORDS * sizeof(uint32_t)>>>(x, qkv_b, proj_b, out);
}